// round 7
// baseline (speedup 1.0000x reference)
#include <cuda_runtime.h>

// Grouped 3-tap width conv with cyclic rolls, fp32.
// Full-K per block (no split-K): grid = 16 k-tiles x 7 heights = 112 blocks.
// 8 chunks of 64 input channels, cp.async double-buffered, f32x2 mainloop,
// register accumulation across chunks, intra-block reduce, plain stores.
// Single kernel node: no memset, no atomics, no grid barrier.
//
// y[o,k,n,m] = sum_{i,j} f[o,i,n,m+j] * w[i,k,j],  f[u] = r[u-1] zero-padded,
// r = width-rolled x; height roll baked into the final store index.

#define NC       8               // chunks
#define CI       64              // input channels per chunk
#define TK       32              // output channels per block (16 pairs (k,k+16))
#define THREADS  1024            // 32 warps = 2 groups x 16 islices

// smem layout (bytes)
#define OFF_IN   0                               // packed input  [2][CI][2][10] float2
#define SZ_IN    (2 * CI * 2 * 10 * 8)           // 20480
#define OFF_WA   (OFF_IN + SZ_IN)                // packed (w0,w1) [2][CI][16] ulonglong2
#define SZ_WA    (2 * CI * 16 * 16)              // 32768
#define OFF_WB   (OFF_WA + SZ_WA)                // packed w2 [2][CI][16] ull
#define SZ_WB    (2 * CI * 16 * 8)               // 16384
#define OFF_RIN  (OFF_WB + SZ_WB)                // raw input [2][896] float
#define SZ_RIN   (2 * 896 * 4)                   // 7168
#define OFF_RW   (OFF_RIN + SZ_RIN)              // raw weights [2][CI*96] float
#define SZ_RW    (2 * CI * 96 * 4)               // 49152
#define SMEM_TOT (OFF_RW + SZ_RW)                // 125952

typedef unsigned long long ull;

__device__ __forceinline__ ull ffma2(ull a, ull b, ull c)
{
    ull d;
    asm("fma.rn.f32x2 %0, %1, %2, %3;" : "=l"(d) : "l"(a), "l"(b), "l"(c));
    return d;
}
__device__ __forceinline__ ull fadd2(ull a, ull b)
{
    ull d;
    asm("add.rn.f32x2 %0, %1, %2;" : "=l"(d) : "l"(a), "l"(b));
    return d;
}
__device__ __forceinline__ void cp16(unsigned saddr, const void* g)
{
    asm volatile("cp.async.cg.shared.global [%0], [%1], 16;" :: "r"(saddr), "l"(g));
}
__device__ __forceinline__ void cp4(unsigned saddr, const void* g)
{
    asm volatile("cp.async.ca.shared.global [%0], [%1], 4;" :: "r"(saddr), "l"(g));
}

__global__ __launch_bounds__(THREADS, 1) void conv_full(const float* __restrict__ x,
                                                        const float* __restrict__ w,
                                                        float* __restrict__ out)
{
    extern __shared__ char dynsmem[];
    float2*      sIn  = reinterpret_cast<float2*>(dynsmem + OFF_IN);   // [(b*CI+i)*2+o][10]
    ulonglong2*  sWa  = reinterpret_cast<ulonglong2*>(dynsmem + OFF_WA);
    ull*         sWb  = reinterpret_cast<ull*>(dynsmem + OFF_WB);
    const float* rIn  = reinterpret_cast<const float*>(dynsmem + OFF_RIN);
    const float* rW   = reinterpret_cast<const float*>(dynsmem + OFF_RW);

    const unsigned sbase = (unsigned)__cvta_generic_to_shared(dynsmem);
    const int tid = threadIdx.x;
    const int kb  = blockIdx.x;        // 0..15
    const int n   = blockIdx.y;        // 0..6
    const int k0  = kb * TK;

    // ---- per-thread cp.async source pointers (advance by fixed stride per chunk)
    // input: thread e<896: e = (o*CI + i)*7 + mw
    const float* pInSrc = 0;
    int in_o = 0, in_i = 0, in_mw = 0;
    if (tid < 896) {
        int e  = tid;
        int t7 = e / 7;  in_mw = e - t7 * 7;
        in_i   = t7 & (CI - 1);
        in_o   = t7 >> 6;
        pInSrc = x + (in_o * 512 + in_i) * 49 + n * 7 + in_mw;
    }
    // weights: float4 entries c4 = tid, tid+1024 (<1536): c4 = i*24 + q
    int w_i0 = tid / 24, w_q0 = tid - w_i0 * 24;
    int c41 = tid + 1024;
    int w_i1 = c41 / 24, w_q1 = c41 - w_i1 * 24;
    const float* pWSrc0 = w + w_i0 * 1536 + kb * 96 + w_q0 * 4;
    const float* pWSrc1 = w + w_i1 * 1536 + kb * 96 + w_q1 * 4;

    // ---- zero-pad packed-input slots u in {0,8,9}, both buffers ----
    if (tid < 768) {
        int e  = tid;
        int u3 = e % 3;
        int r  = e / 3;
        int u  = (u3 == 0) ? 0 : (7 + u3);
        sIn[(r) * 10 + u] = make_float2(0.f, 0.f);   // r enumerates (b*CI+i)*2+o = 0..255... 
    }
    // r above runs 0..255 exactly = 2*CI*2 entries ✓

    // ---- issue chunks 0 and 1 ----
#pragma unroll 1
    for (int c = 0; c < 2; c++) {
        int b = c;
        if (tid < 896) cp4(sbase + OFF_RIN + b * 3584 + tid * 4,
                           pInSrc + c * (CI * 49));
        cp16(sbase + OFF_RW + b * 24576 + tid * 16, pWSrc0 + c * (CI * 1536));
        if (c41 < 1536) cp16(sbase + OFF_RW + b * 24576 + c41 * 16,
                             pWSrc1 + c * (CI * 1536));
        asm volatile("cp.async.commit_group;");
    }

    // ---- thread roles for compute ----
    const int warp   = tid >> 5;           // 0..31
    const int lane   = tid & 31;
    const int og     = warp >> 4;          // group o
    const int islice = warp & 15;
    const int isub   = lane >> 4;
    const int kp     = lane & 15;

    ull A[7];
#pragma unroll
    for (int m = 0; m < 7; m++) A[m] = 0ull;

    // ---- pipelined chunk loop ----
#pragma unroll 1
    for (int c = 0; c < NC; c++) {
        const int b = c & 1;
        if (c < NC - 1) asm volatile("cp.async.wait_group 1;");
        else            asm volatile("cp.async.wait_group 0;");
        __syncthreads();                  // raw[b] visible; compute c-1 done

        // repack input: 896 entries
        if (tid < 896) {
            float v = rIn[b * 896 + tid];
            int u = (in_mw == 6) ? 1 : (in_mw + 2);
            sIn[((b * CI + in_i) * 2 + in_o) * 10 + u] = make_float2(v, v);
        }
        // repack weights: 1024 entries (i = tid>>4, kp' = tid&15)
        {
            int i  = tid >> 4;
            int kq = tid & 15;
            const float* rw = &rW[b * (CI * 96) + i * 96];
            float wa0 = rw[kq * 3 + 0],        wa1 = rw[kq * 3 + 1],        wa2 = rw[kq * 3 + 2];
            float wb0 = rw[(kq + 16) * 3 + 0], wb1 = rw[(kq + 16) * 3 + 1], wb2 = rw[(kq + 16) * 3 + 2];
            float4 pa = make_float4(wa0, wb0, wa1, wb1);
            *reinterpret_cast<float4*>(&sWa[(b * CI + i) * 16 + kq]) = pa;
            float2 pb = make_float2(wa2, wb2);
            sWb[(b * CI + i) * 16 + kq] = *reinterpret_cast<ull*>(&pb);
        }
        __syncthreads();                  // packed[b] ready; raw[b] free

        // prefetch chunk c+2 into raw[b]
        if (c + 2 < NC) {
            int cc = c + 2;
            if (tid < 896) cp4(sbase + OFF_RIN + b * 3584 + tid * 4,
                               pInSrc + cc * (CI * 49));
            cp16(sbase + OFF_RW + b * 24576 + tid * 16, pWSrc0 + cc * (CI * 1536));
            if (c41 < 1536) cp16(sbase + OFF_RW + b * 24576 + c41 * 16,
                                 pWSrc1 + cc * (CI * 1536));
        }
        asm volatile("cp.async.commit_group;");   // uniform group count on all threads

        // compute chunk c: 2 i's per lane
#pragma unroll
        for (int t = 0; t < 2; t++) {
            const int i = islice * 4 + isub * 2 + t;
            const ulonglong2* pr =
                reinterpret_cast<const ulonglong2*>(&sIn[((b * CI + i) * 2 + og) * 10]);
            ulonglong2 L0 = pr[0];   // p0,p1
            ulonglong2 L1 = pr[1];   // p2,p3
            ulonglong2 L2 = pr[2];   // p4,p5
            ulonglong2 L3 = pr[3];   // p6,p7
            ulonglong2 L4 = pr[4];   // p8,pad
            ulonglong2 W01 = sWa[(b * CI + i) * 16 + kp];
            ull        W2  = sWb[(b * CI + i) * 16 + kp];
            ull p0 = L0.x, p1 = L0.y, p2 = L1.x, p3 = L1.y;
            ull p4 = L2.x, p5 = L2.y, p6 = L3.x, p7 = L3.y, p8 = L4.x;

            A[0] = ffma2(p0, W01.x, A[0]); A[0] = ffma2(p1, W01.y, A[0]); A[0] = ffma2(p2, W2, A[0]);
            A[1] = ffma2(p1, W01.x, A[1]); A[1] = ffma2(p2, W01.y, A[1]); A[1] = ffma2(p3, W2, A[1]);
            A[2] = ffma2(p2, W01.x, A[2]); A[2] = ffma2(p3, W01.y, A[2]); A[2] = ffma2(p4, W2, A[2]);
            A[3] = ffma2(p3, W01.x, A[3]); A[3] = ffma2(p4, W01.y, A[3]); A[3] = ffma2(p5, W2, A[3]);
            A[4] = ffma2(p4, W01.x, A[4]); A[4] = ffma2(p5, W01.y, A[4]); A[4] = ffma2(p6, W2, A[4]);
            A[5] = ffma2(p5, W01.x, A[5]); A[5] = ffma2(p6, W01.y, A[5]); A[5] = ffma2(p7, W2, A[5]);
            A[6] = ffma2(p6, W01.x, A[6]); A[6] = ffma2(p7, W01.y, A[6]); A[6] = ffma2(p8, W2, A[6]);
        }
    }

    // ---- reduce: merge isub (shfl), then islices via smem ----
#pragma unroll
    for (int m = 0; m < 7; m++) {
        ull other = __shfl_xor_sync(0xffffffffu, A[m], 16);
        A[m] = fadd2(A[m], other);
    }

    float2* red = reinterpret_cast<float2*>(dynsmem);  // 3584 float2 = 28672 B, buffers dead
    __syncthreads();
    if (isub == 0) {
#pragma unroll
        for (int m = 0; m < 7; m++)
            red[(((og * 16 + kp) * 7) + m) * 16 + islice] = *reinterpret_cast<float2*>(&A[m]);
    }
    __syncthreads();

    if (tid < 224) {                      // (o, kp', m)
        int o  = tid / 112;
        int r  = tid - o * 112;
        int kq = r / 7;
        int m  = r - kq * 7;
        const float2* src = &red[((o * 16 + kq) * 7 + m) * 16];
        float sx = 0.f, sy = 0.f;
#pragma unroll
        for (int is = 0; is < 16; is++) { sx += src[is].x; sy += src[is].y; }
        int nOut = n + 1; if (nOut == 7) nOut = 0;     // height roll +1
        int c1 = o * 512 + k0 + kq;
        out[c1 * 49 + nOut * 7 + m]        = sx;
        out[(c1 + 16) * 49 + nOut * 7 + m] = sy;
    }
}

extern "C" void kernel_launch(void* const* d_in, const int* in_sizes, int n_in,
                              void* d_out, int out_size)
{
    const float* x = (const float*)d_in[0];
    const float* w = (const float*)d_in[1];
    float* out = (float*)d_out;

    cudaFuncSetAttribute(conv_full, cudaFuncAttributeMaxDynamicSharedMemorySize, SMEM_TOT);
    conv_full<<<dim3(16, 7), THREADS, SMEM_TOT>>>(x, w, out);
}